// round 1
// baseline (speedup 1.0000x reference)
#include <cuda_runtime.h>
#include <math.h>

#define EDIM 1024
#define MAXB 8192

// Scratch (static device globals; no runtime allocation)
__device__ float    g_An[(size_t)MAXB * EDIM];
__device__ float    g_Pn[(size_t)MAXB * EDIM];
__device__ float    g_ap[MAXB];
__device__ unsigned g_neg[MAXB];   // encoded float-min per row

// Order-preserving float <-> uint encoding for atomicMin on floats
__device__ __forceinline__ unsigned fenc(float f) {
    unsigned u = __float_as_uint(f);
    return (u & 0x80000000u) ? ~u : (u | 0x80000000u);
}
__device__ __forceinline__ float fdec(unsigned e) {
    unsigned u = (e & 0x80000000u) ? (e ^ 0x80000000u) : ~e;
    return __uint_as_float(u);
}

// ---------------------------------------------------------------------------
// Kernel 1: per-row normalize, ap = cos(anchor, positive), init g_neg
// One block per row, 256 threads, one float4 per thread (E = 1024).
// ---------------------------------------------------------------------------
__global__ __launch_bounds__(256) void normalize_kernel(
    const float* __restrict__ A, const float* __restrict__ P)
{
    const int r   = blockIdx.x;
    const int tid = threadIdx.x;

    const float4 av = reinterpret_cast<const float4*>(A + (size_t)r * EDIM)[tid];
    const float4 pv = reinterpret_cast<const float4*>(P + (size_t)r * EDIM)[tid];

    float sa  = av.x*av.x + av.y*av.y + av.z*av.z + av.w*av.w;
    float sp  = pv.x*pv.x + pv.y*pv.y + pv.z*pv.z + pv.w*pv.w;
    float sap = av.x*pv.x + av.y*pv.y + av.z*pv.z + av.w*pv.w;

    #pragma unroll
    for (int o = 16; o > 0; o >>= 1) {
        sa  += __shfl_xor_sync(0xffffffffu, sa,  o);
        sp  += __shfl_xor_sync(0xffffffffu, sp,  o);
        sap += __shfl_xor_sync(0xffffffffu, sap, o);
    }

    __shared__ float sh[3][8];
    __shared__ float bc[2];
    const int w = tid >> 5, l = tid & 31;
    if (l == 0) { sh[0][w] = sa; sh[1][w] = sp; sh[2][w] = sap; }
    __syncthreads();

    if (tid == 0) {
        float ta = 0.f, tp = 0.f, tap = 0.f;
        #pragma unroll
        for (int i = 0; i < 8; ++i) { ta += sh[0][i]; tp += sh[1][i]; tap += sh[2][i]; }
        float na = sqrtf(ta), np = sqrtf(tp);
        g_ap[r]  = tap / fmaxf(na * np, 1e-8f);
        g_neg[r] = 0xFFFFFFFFu;               // +inf under fenc ordering
        bc[0] = rsqrtf(ta);
        bc[1] = rsqrtf(tp);
    }
    __syncthreads();

    const float rna = bc[0], rnp = bc[1];
    float4 an = make_float4(av.x*rna, av.y*rna, av.z*rna, av.w*rna);
    float4 pn = make_float4(pv.x*rnp, pv.y*rnp, pv.z*rnp, pv.w*rnp);
    reinterpret_cast<float4*>(g_An + (size_t)r * EDIM)[tid] = an;
    reinterpret_cast<float4*>(g_Pn + (size_t)r * EDIM)[tid] = pn;
}

// ---------------------------------------------------------------------------
// Kernel 2: fused sim = An * Pn^T with per-row running min (j != i).
// 128x128 block tile, BK=16, 256 threads, 8x8 register micro-tile.
// No sim matrix materialization; epilogue shuffle-reduces to per-row min
// and atomicMin's into g_neg (encoded).
// ---------------------------------------------------------------------------
__global__ __launch_bounds__(256) void gemm_min_kernel()
{
    __shared__ float As[16][128];
    __shared__ float Bs[16][128];

    const int tid  = threadIdx.x;
    const int row0 = blockIdx.y * 128;
    const int col0 = blockIdx.x * 128;
    const int ty   = tid >> 4;   // 0..15
    const int tx   = tid & 15;   // 0..15

    float acc[8][8];
    #pragma unroll
    for (int m = 0; m < 8; ++m)
        #pragma unroll
        for (int n = 0; n < 8; ++n) acc[m][n] = 0.f;

    for (int k0 = 0; k0 < EDIM; k0 += 16) {
        // Load 128x16 tiles of An and Pn, store transposed into smem
        #pragma unroll
        for (int it = 0; it < 2; ++it) {
            int lin = it * 256 + tid;      // 0..511
            int r   = lin >> 2;            // 0..127
            int c4  = (lin & 3) * 4;       // 0,4,8,12
            float4 va = *reinterpret_cast<const float4*>(
                g_An + (size_t)(row0 + r) * EDIM + k0 + c4);
            As[c4 + 0][r] = va.x; As[c4 + 1][r] = va.y;
            As[c4 + 2][r] = va.z; As[c4 + 3][r] = va.w;
            float4 vb = *reinterpret_cast<const float4*>(
                g_Pn + (size_t)(col0 + r) * EDIM + k0 + c4);
            Bs[c4 + 0][r] = vb.x; Bs[c4 + 1][r] = vb.y;
            Bs[c4 + 2][r] = vb.z; Bs[c4 + 3][r] = vb.w;
        }
        __syncthreads();

        #pragma unroll
        for (int kk = 0; kk < 16; ++kk) {
            float4 a0 = *reinterpret_cast<const float4*>(&As[kk][ty * 4]);
            float4 a1 = *reinterpret_cast<const float4*>(&As[kk][64 + ty * 4]);
            float4 b0 = *reinterpret_cast<const float4*>(&Bs[kk][tx * 4]);
            float4 b1 = *reinterpret_cast<const float4*>(&Bs[kk][64 + tx * 4]);
            float ar[8] = {a0.x, a0.y, a0.z, a0.w, a1.x, a1.y, a1.z, a1.w};
            float br[8] = {b0.x, b0.y, b0.z, b0.w, b1.x, b1.y, b1.z, b1.w};
            #pragma unroll
            for (int m = 0; m < 8; ++m)
                #pragma unroll
                for (int n = 0; n < 8; ++n)
                    acc[m][n] = fmaf(ar[m], br[n], acc[m][n]);
        }
        __syncthreads();
    }

    // Epilogue: per-row min over the 128-column tile, excluding diagonal.
    #pragma unroll
    for (int m = 0; m < 8; ++m) {
        const int gi = row0 + ((m < 4) ? (ty * 4 + m) : (64 + ty * 4 + (m - 4)));
        float mn = 3.0e38f;
        #pragma unroll
        for (int n = 0; n < 8; ++n) {
            const int gj = col0 + ((n < 4) ? (tx * 4 + n) : (64 + tx * 4 + (n - 4)));
            if (gi != gj) mn = fminf(mn, acc[m][n]);
        }
        // Reduce across the 16 lanes sharing this row (tx dimension).
        #pragma unroll
        for (int o = 8; o > 0; o >>= 1)
            mn = fminf(mn, __shfl_xor_sync(0xffffffffu, mn, o));
        if (tx == 0) atomicMin(&g_neg[gi], fenc(mn));
    }
}

// ---------------------------------------------------------------------------
// Kernel 3: loss = mean(relu(1 + ap - an))
// ---------------------------------------------------------------------------
__global__ __launch_bounds__(256) void loss_kernel(float* __restrict__ out, int B)
{
    const int tid = threadIdx.x;
    float s = 0.f;
    for (int r = tid; r < B; r += 256) {
        float an = fdec(g_neg[r]);
        s += fmaxf(1.0f + g_ap[r] - an, 0.f);
    }
    #pragma unroll
    for (int o = 16; o > 0; o >>= 1) s += __shfl_xor_sync(0xffffffffu, s, o);

    __shared__ float sh[8];
    const int w = tid >> 5, l = tid & 31;
    if (l == 0) sh[w] = s;
    __syncthreads();
    if (tid == 0) {
        float t = 0.f;
        #pragma unroll
        for (int i = 0; i < 8; ++i) t += sh[i];
        out[0] = t / (float)B;
    }
}

extern "C" void kernel_launch(void* const* d_in, const int* in_sizes, int n_in,
                              void* d_out, int out_size)
{
    const float* anchor   = (const float*)d_in[0];
    const float* positive = (const float*)d_in[1];
    float* out = (float*)d_out;

    const int B = in_sizes[0] / EDIM;   // 8192

    normalize_kernel<<<B, 256>>>(anchor, positive);
    dim3 grid(B / 128, B / 128);
    gemm_min_kernel<<<grid, 256>>>();
    loss_kernel<<<1, 256>>>(out, B);
}

// round 3
// speedup vs baseline: 6.1658x; 6.1658x over previous
#include <cuda_runtime.h>
#include <cuda_bf16.h>
#include <math.h>
#include <stdint.h>

#define EDIM   1024
#define BDIM   8192
#define TM     128
#define TN     256
#define BK     32                  // bf16 elems per stage (64 bytes/row)
#define NCHUNK (EDIM / BK)         // 32
#define STAGES 4

#define A_STAGE_BYTES (TM * BK * 2)                      // 8192
#define B_STAGE_BYTES (TN * BK * 2)                      // 16384
#define B_BASE_OFF    (STAGES * A_STAGE_BYTES)           // 32768
#define SMEM_DYN      (STAGES * (A_STAGE_BYTES + B_STAGE_BYTES))  // 98304

// ---------------- static device scratch (no runtime alloc) ----------------
__device__ __align__(256) __nv_bfloat16 g_Anh[(size_t)BDIM * EDIM];
__device__ __align__(256) __nv_bfloat16 g_Pnh[(size_t)BDIM * EDIM];
__device__ float    g_ap[BDIM];
__device__ unsigned g_neg[BDIM];

// Order-preserving float <-> uint encoding for atomicMin on floats
__device__ __forceinline__ unsigned fenc(float f) {
    unsigned u = __float_as_uint(f);
    return (u & 0x80000000u) ? ~u : (u | 0x80000000u);
}
__device__ __forceinline__ float fdec(unsigned e) {
    unsigned u = (e & 0x80000000u) ? (e ^ 0x80000000u) : ~e;
    return __uint_as_float(u);
}

#define CP_ASYNC16(dst, src) \
    asm volatile("cp.async.cg.shared.global [%0], [%1], 16;" :: "r"(dst), "l"(src))
#define CP_COMMIT() asm volatile("cp.async.commit_group;" ::: "memory")
#define CP_WAIT(n)  asm volatile("cp.async.wait_group %0;" :: "n"(n) : "memory")

__device__ __forceinline__ void ldsm_x4(uint32_t& r0, uint32_t& r1,
                                        uint32_t& r2, uint32_t& r3, uint32_t a) {
    asm volatile("ldmatrix.sync.aligned.m8n8.x4.shared.b16 {%0,%1,%2,%3}, [%4];"
                 : "=r"(r0), "=r"(r1), "=r"(r2), "=r"(r3) : "r"(a));
}

__device__ __forceinline__ void mma16816(float& c0, float& c1, float& c2, float& c3,
                                         uint32_t a0, uint32_t a1, uint32_t a2, uint32_t a3,
                                         uint32_t b0, uint32_t b1) {
    asm volatile(
        "mma.sync.aligned.m16n8k16.row.col.f32.bf16.bf16.f32 "
        "{%0,%1,%2,%3}, {%4,%5,%6,%7}, {%8,%9}, {%0,%1,%2,%3};"
        : "+f"(c0), "+f"(c1), "+f"(c2), "+f"(c3)
        : "r"(a0), "r"(a1), "r"(a2), "r"(a3), "r"(b0), "r"(b1));
}

// Swizzled byte offset within a [rows][BK] bf16 tile (64B rows, 16B chunks)
__device__ __forceinline__ uint32_t sw_off(int r, int c) {
    return (uint32_t)(r * 64 + ((c ^ ((r >> 1) & 3)) << 4));
}

// ---------------------------------------------------------------------------
// Kernel 1: per-row normalize (bf16 out), ap = cos(anchor,positive), init neg
// ---------------------------------------------------------------------------
__global__ __launch_bounds__(256) void normalize_kernel(
    const float* __restrict__ A, const float* __restrict__ P)
{
    const int r   = blockIdx.x;
    const int tid = threadIdx.x;

    const float4 av = reinterpret_cast<const float4*>(A + (size_t)r * EDIM)[tid];
    const float4 pv = reinterpret_cast<const float4*>(P + (size_t)r * EDIM)[tid];

    float sa  = av.x*av.x + av.y*av.y + av.z*av.z + av.w*av.w;
    float sp  = pv.x*pv.x + pv.y*pv.y + pv.z*pv.z + pv.w*pv.w;
    float sap = av.x*pv.x + av.y*pv.y + av.z*pv.z + av.w*pv.w;

    #pragma unroll
    for (int o = 16; o > 0; o >>= 1) {
        sa  += __shfl_xor_sync(0xffffffffu, sa,  o);
        sp  += __shfl_xor_sync(0xffffffffu, sp,  o);
        sap += __shfl_xor_sync(0xffffffffu, sap, o);
    }

    __shared__ float sh[3][8];
    __shared__ float bc[2];
    const int w = tid >> 5, l = tid & 31;
    if (l == 0) { sh[0][w] = sa; sh[1][w] = sp; sh[2][w] = sap; }
    __syncthreads();

    if (tid == 0) {
        float ta = 0.f, tp = 0.f, tap = 0.f;
        #pragma unroll
        for (int i = 0; i < 8; ++i) { ta += sh[0][i]; tp += sh[1][i]; tap += sh[2][i]; }
        g_ap[r]  = tap / fmaxf(sqrtf(ta) * sqrtf(tp), 1e-8f);
        g_neg[r] = 0xFFFFFFFFu;        // +inf under fenc ordering
        bc[0] = rsqrtf(ta);
        bc[1] = rsqrtf(tp);
    }
    __syncthreads();

    const float rna = bc[0], rnp = bc[1];
    __nv_bfloat162* da = reinterpret_cast<__nv_bfloat162*>(g_Anh + (size_t)r * EDIM);
    __nv_bfloat162* dp = reinterpret_cast<__nv_bfloat162*>(g_Pnh + (size_t)r * EDIM);
    da[tid*2 + 0] = __floats2bfloat162_rn(av.x * rna, av.y * rna);
    da[tid*2 + 1] = __floats2bfloat162_rn(av.z * rna, av.w * rna);
    dp[tid*2 + 0] = __floats2bfloat162_rn(pv.x * rnp, pv.y * rnp);
    dp[tid*2 + 1] = __floats2bfloat162_rn(pv.z * rnp, pv.w * rnp);
}

// ---------------------------------------------------------------------------
// Kernel 2: bf16 mma.sync GEMM (An * Pn^T) with fused per-row min epilogue.
// 128x256 CTA tile, BK=32, 4-stage cp.async pipeline, 8 warps (64x64 each).
// ---------------------------------------------------------------------------
__device__ __forceinline__ void load_stage(uint32_t sbase, int slot, int chunk,
                                           int row0, int col0, int tid)
{
    const size_t k0b = (size_t)chunk * (BK * 2);   // 64 bytes per chunk per row
    const char* Ab = (const char*)g_Anh;
    const char* Bb = (const char*)g_Pnh;

    const uint32_t ad0 = sbase + slot * A_STAGE_BYTES;
    #pragma unroll
    for (int i = 0; i < 2; ++i) {                   // 512 chunks of 16B
        int u = i * 256 + tid;
        int r = u >> 2, c = u & 3;
        CP_ASYNC16(ad0 + sw_off(r, c),
                   Ab + (size_t)(row0 + r) * (EDIM * 2) + k0b + c * 16);
    }
    const uint32_t bd0 = sbase + B_BASE_OFF + slot * B_STAGE_BYTES;
    #pragma unroll
    for (int i = 0; i < 4; ++i) {                   // 1024 chunks of 16B
        int u = i * 256 + tid;
        int r = u >> 2, c = u & 3;
        CP_ASYNC16(bd0 + sw_off(r, c),
                   Bb + (size_t)(col0 + r) * (EDIM * 2) + k0b + c * 16);
    }
}

__global__ __launch_bounds__(256, 1) void gemm_min_mma()
{
    extern __shared__ char dynsmem[];
    const uint32_t sbase = (uint32_t)__cvta_generic_to_shared(dynsmem);

    const int tid   = threadIdx.x;
    const int wid   = tid >> 5;
    const int lane  = tid & 31;
    const int wm    = wid >> 2;          // 0..1
    const int wn    = wid & 3;           // 0..3
    const int row0  = blockIdx.y * TM;
    const int col0  = blockIdx.x * TN;

    const int mi = lane >> 3;            // ldmatrix matrix index 0..3
    const int lr = lane & 7;

    float acc[4][8][4];
    #pragma unroll
    for (int mt = 0; mt < 4; ++mt)
        #pragma unroll
        for (int nf = 0; nf < 8; ++nf)
            #pragma unroll
            for (int e = 0; e < 4; ++e) acc[mt][nf][e] = 0.f;

    // Prologue: fill STAGES-1 stages
    #pragma unroll
    for (int s = 0; s < STAGES - 1; ++s) {
        load_stage(sbase, s, s, row0, col0, tid);
        CP_COMMIT();
    }

    for (int c = 0; c < NCHUNK; ++c) {
        const int s = c & (STAGES - 1);

        if      (c <= NCHUNK - 3) CP_WAIT(2);
        else if (c == NCHUNK - 2) CP_WAIT(1);
        else                      CP_WAIT(0);
        __syncthreads();

        if (c + STAGES - 1 < NCHUNK) {
            load_stage(sbase, (c + STAGES - 1) & (STAGES - 1),
                       c + STAGES - 1, row0, col0, tid);
            CP_COMMIT();
        }

        const uint32_t aS = sbase + s * A_STAGE_BYTES;
        const uint32_t bS = sbase + B_BASE_OFF + s * B_STAGE_BYTES;

        #pragma unroll
        for (int h = 0; h < 2; ++h) {          // two k16 halves of BK=32
            uint32_t af[4][4];
            uint32_t bf[8][2];
            #pragma unroll
            for (int mt = 0; mt < 4; ++mt) {
                const int r = wm * 64 + mt * 16 + (mi & 1) * 8 + lr;
                const int ch = 2 * h + (mi >> 1);
                ldsm_x4(af[mt][0], af[mt][1], af[mt][2], af[mt][3],
                        aS + sw_off(r, ch));
            }
            #pragma unroll
            for (int nt = 0; nt < 4; ++nt) {
                const int r = wn * 64 + nt * 16 + (mi & 1) * 8 + lr;
                const int ch = 2 * h + (mi >> 1);
                uint32_t r0, r1, r2, r3;
                ldsm_x4(r0, r1, r2, r3, bS + sw_off(r, ch));
                bf[2*nt][0]   = r0; bf[2*nt][1]   = r2;
                bf[2*nt+1][0] = r1; bf[2*nt+1][1] = r3;
            }
            #pragma unroll
            for (int mt = 0; mt < 4; ++mt)
                #pragma unroll
                for (int nf = 0; nf < 8; ++nf)
                    mma16816(acc[mt][nf][0], acc[mt][nf][1],
                             acc[mt][nf][2], acc[mt][nf][3],
                             af[mt][0], af[mt][1], af[mt][2], af[mt][3],
                             bf[nf][0], bf[nf][1]);
        }
        __syncthreads();
    }

    // Epilogue: per-row min (excluding diagonal), quad-reduce, atomicMin.
    #pragma unroll
    for (int mt = 0; mt < 4; ++mt) {
        const int r_lo = row0 + wm * 64 + mt * 16 + (lane >> 2);
        const int r_hi = r_lo + 8;
        float mlo = 3.0e38f, mhi = 3.0e38f;
        #pragma unroll
        for (int nf = 0; nf < 8; ++nf) {
            #pragma unroll
            for (int e = 0; e < 2; ++e) {
                const int gj = col0 + wn * 64 + nf * 8 + (lane & 3) * 2 + e;
                const float vlo = acc[mt][nf][e];
                const float vhi = acc[mt][nf][2 + e];
                if (gj != r_lo) mlo = fminf(mlo, vlo);
                if (gj != r_hi) mhi = fminf(mhi, vhi);
            }
        }
        mlo = fminf(mlo, __shfl_xor_sync(0xffffffffu, mlo, 1));
        mlo = fminf(mlo, __shfl_xor_sync(0xffffffffu, mlo, 2));
        mhi = fminf(mhi, __shfl_xor_sync(0xffffffffu, mhi, 1));
        mhi = fminf(mhi, __shfl_xor_sync(0xffffffffu, mhi, 2));
        if ((lane & 3) == 0) {
            atomicMin(&g_neg[r_lo], fenc(mlo));
            atomicMin(&g_neg[r_hi], fenc(mhi));
        }
    }
}

// ---------------------------------------------------------------------------
// Kernel 3: loss = mean(relu(1 + ap - an))
// ---------------------------------------------------------------------------
__global__ __launch_bounds__(256) void loss_kernel(float* __restrict__ out, int B)
{
    const int tid = threadIdx.x;
    float s = 0.f;
    for (int r = tid; r < B; r += 256) {
        s += fmaxf(1.0f + g_ap[r] - fdec(g_neg[r]), 0.f);
    }
    #pragma unroll
    for (int o = 16; o > 0; o >>= 1) s += __shfl_xor_sync(0xffffffffu, s, o);

    __shared__ float sh[8];
    const int w = tid >> 5, l = tid & 31;
    if (l == 0) sh[w] = s;
    __syncthreads();
    if (tid == 0) {
        float t = 0.f;
        #pragma unroll
        for (int i = 0; i < 8; ++i) t += sh[i];
        out[0] = t / (float)B;
    }
}

extern "C" void kernel_launch(void* const* d_in, const int* in_sizes, int n_in,
                              void* d_out, int out_size)
{
    const float* anchor   = (const float*)d_in[0];
    const float* positive = (const float*)d_in[1];
    float* out = (float*)d_out;

    const int B = in_sizes[0] / EDIM;   // 8192

    cudaFuncSetAttribute(gemm_min_mma,
                         cudaFuncAttributeMaxDynamicSharedMemorySize, SMEM_DYN);

    normalize_kernel<<<B, 256>>>(anchor, positive);
    dim3 grid(B / TN, B / TM);
    gemm_min_mma<<<grid, 256, SMEM_DYN>>>();
    loss_kernel<<<1, 256>>>(out, B);
}

// round 4
// speedup vs baseline: 6.5215x; 1.0577x over previous
#include <cuda_runtime.h>
#include <cuda_bf16.h>
#include <math.h>
#include <stdint.h>

#define EDIM   1024
#define BDIM   8192
#define TM     128
#define TN     256
#define KB     64                  // BYTES of K per stage per row (=64 fp8 elems)
#define NCHUNK (EDIM / KB)         // 16
#define STAGES 4

#define A_STAGE_BYTES (TM * KB)                          // 8192
#define B_STAGE_BYTES (TN * KB)                          // 16384
#define B_BASE_OFF    (STAGES * A_STAGE_BYTES)           // 32768
#define SMEM_DYN      (STAGES * (A_STAGE_BYTES + B_STAGE_BYTES))  // 98304

#define FP8_SCALE 16.0f            // x16 before e4m3 quantization

// ---------------- static device scratch (no runtime alloc) ----------------
__device__ __align__(256) uint8_t g_A8[(size_t)BDIM * EDIM];
__device__ __align__(256) uint8_t g_P8[(size_t)BDIM * EDIM];
__device__ float              g_ap[BDIM];
__device__ float              g_rna[BDIM];
__device__ float              g_rnp[BDIM];
__device__ unsigned long long g_neg[BDIM];   // (fenc(val)<<32) | col_idx
__device__ float              g_term[BDIM];

// Order-preserving float -> uint encoding (for packed 64-bit atomicMin)
__device__ __forceinline__ unsigned fenc(float f) {
    unsigned u = __float_as_uint(f);
    return (u & 0x80000000u) ? ~u : (u | 0x80000000u);
}

#define CP_ASYNC16(dst, src) \
    asm volatile("cp.async.cg.shared.global [%0], [%1], 16;" :: "r"(dst), "l"(src))
#define CP_COMMIT() asm volatile("cp.async.commit_group;" ::: "memory")
#define CP_WAIT(n)  asm volatile("cp.async.wait_group %0;" :: "n"(n) : "memory")

__device__ __forceinline__ void ldsm_x4(uint32_t& r0, uint32_t& r1,
                                        uint32_t& r2, uint32_t& r3, uint32_t a) {
    asm volatile("ldmatrix.sync.aligned.m8n8.x4.shared.b16 {%0,%1,%2,%3}, [%4];"
                 : "=r"(r0), "=r"(r1), "=r"(r2), "=r"(r3) : "r"(a));
}

// fp8 e4m3 MMA: m16n8k32, fragments byte-identical to bf16 m16n8k16
__device__ __forceinline__ void mma_fp8(float& c0, float& c1, float& c2, float& c3,
                                        uint32_t a0, uint32_t a1, uint32_t a2, uint32_t a3,
                                        uint32_t b0, uint32_t b1) {
    asm volatile(
        "mma.sync.aligned.m16n8k32.row.col.f32.e4m3.e4m3.f32 "
        "{%0,%1,%2,%3}, {%4,%5,%6,%7}, {%8,%9}, {%0,%1,%2,%3};"
        : "+f"(c0), "+f"(c1), "+f"(c2), "+f"(c3)
        : "r"(a0), "r"(a1), "r"(a2), "r"(a3), "r"(b0), "r"(b1));
}

// pack 4 floats -> 4 e4m3 bytes (satfinite), memory order x0..x3
__device__ __forceinline__ uint32_t pack_e4m3x4(float x0, float x1, float x2, float x3) {
    uint16_t h0, h1;
    asm("cvt.rn.satfinite.e4m3x2.f32 %0, %1, %2;" : "=h"(h0) : "f"(x1), "f"(x0));
    asm("cvt.rn.satfinite.e4m3x2.f32 %0, %1, %2;" : "=h"(h1) : "f"(x3), "f"(x2));
    return (uint32_t)h0 | ((uint32_t)h1 << 16);
}

// Swizzled byte offset within a [rows][64B] tile (64B rows, 16B chunks)
__device__ __forceinline__ uint32_t sw_off(int r, int c) {
    return (uint32_t)(r * 64 + ((c ^ ((r >> 1) & 3)) << 4));
}

// ---------------------------------------------------------------------------
// Kernel 1: per-row norms, ap (exact fp32), fp8 quantized normalized vectors
// ---------------------------------------------------------------------------
__global__ __launch_bounds__(256) void normalize_kernel(
    const float* __restrict__ A, const float* __restrict__ P)
{
    const int r   = blockIdx.x;
    const int tid = threadIdx.x;

    const float4 av = reinterpret_cast<const float4*>(A + (size_t)r * EDIM)[tid];
    const float4 pv = reinterpret_cast<const float4*>(P + (size_t)r * EDIM)[tid];

    float sa  = av.x*av.x + av.y*av.y + av.z*av.z + av.w*av.w;
    float sp  = pv.x*pv.x + pv.y*pv.y + pv.z*pv.z + pv.w*pv.w;
    float sap = av.x*pv.x + av.y*pv.y + av.z*pv.z + av.w*pv.w;

    #pragma unroll
    for (int o = 16; o > 0; o >>= 1) {
        sa  += __shfl_xor_sync(0xffffffffu, sa,  o);
        sp  += __shfl_xor_sync(0xffffffffu, sp,  o);
        sap += __shfl_xor_sync(0xffffffffu, sap, o);
    }

    __shared__ float sh[3][8];
    __shared__ float bc[2];
    const int w = tid >> 5, l = tid & 31;
    if (l == 0) { sh[0][w] = sa; sh[1][w] = sp; sh[2][w] = sap; }
    __syncthreads();

    if (tid == 0) {
        float ta = 0.f, tp = 0.f, tap = 0.f;
        #pragma unroll
        for (int i = 0; i < 8; ++i) { ta += sh[0][i]; tp += sh[1][i]; tap += sh[2][i]; }
        g_ap[r]  = tap / fmaxf(sqrtf(ta) * sqrtf(tp), 1e-8f);
        float rna = rsqrtf(ta), rnp = rsqrtf(tp);
        g_rna[r] = rna;
        g_rnp[r] = rnp;
        g_neg[r] = 0xFFFFFFFFFFFFFFFFull;
        bc[0] = rna * FP8_SCALE;
        bc[1] = rnp * FP8_SCALE;
    }
    __syncthreads();

    const float qa = bc[0], qp = bc[1];
    reinterpret_cast<uint32_t*>(g_A8 + (size_t)r * EDIM)[tid] =
        pack_e4m3x4(av.x * qa, av.y * qa, av.z * qa, av.w * qa);
    reinterpret_cast<uint32_t*>(g_P8 + (size_t)r * EDIM)[tid] =
        pack_e4m3x4(pv.x * qp, pv.y * qp, pv.z * qp, pv.w * qp);
}

// ---------------------------------------------------------------------------
// Kernel 2: fp8 mma.sync GEMM (A8 * P8^T) with fused per-row argmin epilogue.
// 128x256 CTA tile, 64B K-chunks, 4-stage cp.async pipeline, 8 warps.
// ---------------------------------------------------------------------------
__device__ __forceinline__ void load_stage(uint32_t sbase, int slot, int chunk,
                                           int row0, int col0, int tid)
{
    const size_t k0b = (size_t)chunk * KB;
    const char* Ab = (const char*)g_A8;
    const char* Bb = (const char*)g_P8;

    const uint32_t ad0 = sbase + slot * A_STAGE_BYTES;
    #pragma unroll
    for (int i = 0; i < 2; ++i) {                   // 512 chunks of 16B
        int u = i * 256 + tid;
        int r = u >> 2, c = u & 3;
        CP_ASYNC16(ad0 + sw_off(r, c),
                   Ab + (size_t)(row0 + r) * EDIM + k0b + c * 16);
    }
    const uint32_t bd0 = sbase + B_BASE_OFF + slot * B_STAGE_BYTES;
    #pragma unroll
    for (int i = 0; i < 4; ++i) {                   // 1024 chunks of 16B
        int u = i * 256 + tid;
        int r = u >> 2, c = u & 3;
        CP_ASYNC16(bd0 + sw_off(r, c),
                   Bb + (size_t)(col0 + r) * EDIM + k0b + c * 16);
    }
}

__global__ __launch_bounds__(256, 1) void gemm_min_fp8()
{
    extern __shared__ char dynsmem[];
    const uint32_t sbase = (uint32_t)__cvta_generic_to_shared(dynsmem);

    const int tid   = threadIdx.x;
    const int wid   = tid >> 5;
    const int lane  = tid & 31;
    const int wm    = wid >> 2;          // 0..1
    const int wn    = wid & 3;           // 0..3
    const int row0  = blockIdx.y * TM;
    const int col0  = blockIdx.x * TN;

    const int mi = lane >> 3;
    const int lr = lane & 7;

    float acc[4][8][4];
    #pragma unroll
    for (int mt = 0; mt < 4; ++mt)
        #pragma unroll
        for (int nf = 0; nf < 8; ++nf)
            #pragma unroll
            for (int e = 0; e < 4; ++e) acc[mt][nf][e] = 0.f;

    #pragma unroll
    for (int s = 0; s < STAGES - 1; ++s) {
        load_stage(sbase, s, s, row0, col0, tid);
        CP_COMMIT();
    }

    for (int c = 0; c < NCHUNK; ++c) {
        const int s = c & (STAGES - 1);

        if      (c <= NCHUNK - 3) CP_WAIT(2);
        else if (c == NCHUNK - 2) CP_WAIT(1);
        else                      CP_WAIT(0);
        __syncthreads();

        if (c + STAGES - 1 < NCHUNK) {
            load_stage(sbase, (c + STAGES - 1) & (STAGES - 1),
                       c + STAGES - 1, row0, col0, tid);
            CP_COMMIT();
        }

        const uint32_t aS = sbase + s * A_STAGE_BYTES;
        const uint32_t bS = sbase + B_BASE_OFF + s * B_STAGE_BYTES;

        #pragma unroll
        for (int h = 0; h < 2; ++h) {          // two k32 halves of 64B chunk
            uint32_t af[4][4];
            uint32_t bf[8][2];
            #pragma unroll
            for (int mt = 0; mt < 4; ++mt) {
                const int r = wm * 64 + mt * 16 + (mi & 1) * 8 + lr;
                const int ch = 2 * h + (mi >> 1);
                ldsm_x4(af[mt][0], af[mt][1], af[mt][2], af[mt][3],
                        aS + sw_off(r, ch));
            }
            #pragma unroll
            for (int nt = 0; nt < 4; ++nt) {
                const int r = wn * 64 + nt * 16 + (mi & 1) * 8 + lr;
                const int ch = 2 * h + (mi >> 1);
                uint32_t r0, r1, r2, r3;
                ldsm_x4(r0, r1, r2, r3, bS + sw_off(r, ch));
                bf[2*nt][0]   = r0; bf[2*nt][1]   = r2;
                bf[2*nt+1][0] = r1; bf[2*nt+1][1] = r3;
            }
            #pragma unroll
            for (int mt = 0; mt < 4; ++mt)
                #pragma unroll
                for (int nf = 0; nf < 8; ++nf)
                    mma_fp8(acc[mt][nf][0], acc[mt][nf][1],
                            acc[mt][nf][2], acc[mt][nf][3],
                            af[mt][0], af[mt][1], af[mt][2], af[mt][3],
                            bf[nf][0], bf[nf][1]);
        }
        __syncthreads();
    }

    // Epilogue: per-row (min value, col index) packed argmin, excl. diagonal.
    #pragma unroll
    for (int mt = 0; mt < 4; ++mt) {
        const int r_lo = row0 + wm * 64 + mt * 16 + (lane >> 2);
        const int r_hi = r_lo + 8;
        unsigned long long plo = 0xFFFFFFFFFFFFFFFFull;
        unsigned long long phi = 0xFFFFFFFFFFFFFFFFull;
        #pragma unroll
        for (int nf = 0; nf < 8; ++nf) {
            #pragma unroll
            for (int e = 0; e < 2; ++e) {
                const int gj = col0 + wn * 64 + nf * 8 + (lane & 3) * 2 + e;
                const unsigned long long klo =
                    ((unsigned long long)fenc(acc[mt][nf][e])     << 32) | (unsigned)gj;
                const unsigned long long khi =
                    ((unsigned long long)fenc(acc[mt][nf][2 + e]) << 32) | (unsigned)gj;
                if (gj != r_lo && klo < plo) plo = klo;
                if (gj != r_hi && khi < phi) phi = khi;
            }
        }
        #pragma unroll
        for (int o = 1; o <= 2; o <<= 1) {
            unsigned long long t;
            t = __shfl_xor_sync(0xffffffffu, plo, o); if (t < plo) plo = t;
            t = __shfl_xor_sync(0xffffffffu, phi, o); if (t < phi) phi = t;
        }
        if ((lane & 3) == 0) {
            atomicMin(&g_neg[r_lo], plo);
            atomicMin(&g_neg[r_hi], phi);
        }
    }
}

// ---------------------------------------------------------------------------
// Kernel 3: exact fp32 recompute of an for the selected column; per-row term.
// One block per row.
// ---------------------------------------------------------------------------
__global__ __launch_bounds__(256) void an_term_kernel(
    const float* __restrict__ A, const float* __restrict__ P)
{
    const int r   = blockIdx.x;
    const int tid = threadIdx.x;
    const int j   = (int)(unsigned)(g_neg[r] & 0xFFFFFFFFull);

    const float4 av = reinterpret_cast<const float4*>(A + (size_t)r * EDIM)[tid];
    const float4 pv = reinterpret_cast<const float4*>(P + (size_t)j * EDIM)[tid];
    float s = av.x*pv.x + av.y*pv.y + av.z*pv.z + av.w*pv.w;

    #pragma unroll
    for (int o = 16; o > 0; o >>= 1) s += __shfl_xor_sync(0xffffffffu, s, o);

    __shared__ float sh[8];
    const int w = tid >> 5, l = tid & 31;
    if (l == 0) sh[w] = s;
    __syncthreads();
    if (tid == 0) {
        float t = 0.f;
        #pragma unroll
        for (int i = 0; i < 8; ++i) t += sh[i];
        const float an = t * g_rna[r] * g_rnp[j];
        g_term[r] = fmaxf(1.0f + g_ap[r] - an, 0.f);
    }
}

// ---------------------------------------------------------------------------
// Kernel 4: mean over terms
// ---------------------------------------------------------------------------
__global__ __launch_bounds__(256) void loss_kernel(float* __restrict__ out, int B)
{
    const int tid = threadIdx.x;
    float s = 0.f;
    for (int r = tid; r < B; r += 256) s += g_term[r];
    #pragma unroll
    for (int o = 16; o > 0; o >>= 1) s += __shfl_xor_sync(0xffffffffu, s, o);

    __shared__ float sh[8];
    const int w = tid >> 5, l = tid & 31;
    if (l == 0) sh[w] = s;
    __syncthreads();
    if (tid == 0) {
        float t = 0.f;
        #pragma unroll
        for (int i = 0; i < 8; ++i) t += sh[i];
        out[0] = t / (float)B;
    }
}

extern "C" void kernel_launch(void* const* d_in, const int* in_sizes, int n_in,
                              void* d_out, int out_size)
{
    const float* anchor   = (const float*)d_in[0];
    const float* positive = (const float*)d_in[1];
    float* out = (float*)d_out;

    const int B = in_sizes[0] / EDIM;   // 8192

    cudaFuncSetAttribute(gemm_min_fp8,
                         cudaFuncAttributeMaxDynamicSharedMemorySize, SMEM_DYN);

    normalize_kernel<<<B, 256>>>(anchor, positive);
    dim3 grid(B / TN, B / TM);
    gemm_min_fp8<<<grid, 256, SMEM_DYN>>>();
    an_term_kernel<<<B, 256>>>(anchor, positive);
    loss_kernel<<<1, 256>>>(out, B);
}

// round 5
// speedup vs baseline: 7.3121x; 1.1212x over previous
#include <cuda_runtime.h>
#include <cuda_fp16.h>
#include <math.h>
#include <stdint.h>

#define EDIM   1024
#define BDIM   8192
#define TM     128
#define TN     256
#define BK     32                  // f16 elems per stage per row (64 bytes)
#define NCHUNK (EDIM / BK)         // 32
#define STAGES 4

#define A_STAGE_BYTES (TM * BK * 2)                      // 8192
#define B_STAGE_BYTES (TN * BK * 2)                      // 16384
#define B_BASE_OFF    (STAGES * A_STAGE_BYTES)           // 32768
#define SMEM_DYN      (STAGES * (A_STAGE_BYTES + B_STAGE_BYTES))  // 98304

// ---------------- static device scratch (no runtime alloc) ----------------
__device__ __align__(256) __half g_A16[(size_t)BDIM * EDIM];
__device__ __align__(256) __half g_P16[(size_t)BDIM * EDIM];
__device__ float              g_ap[BDIM];
__device__ float              g_rna[BDIM];
__device__ float              g_rnp[BDIM];
__device__ unsigned long long g_neg[BDIM];   // (fenc(val)<<32) | col_idx
__device__ float              g_term[BDIM];

// Order-preserving float -> uint encoding (for packed 64-bit atomicMin)
__device__ __forceinline__ unsigned fenc(float f) {
    unsigned u = __float_as_uint(f);
    return (u & 0x80000000u) ? ~u : (u | 0x80000000u);
}

#define CP_ASYNC16(dst, src) \
    asm volatile("cp.async.cg.shared.global [%0], [%1], 16;" :: "r"(dst), "l"(src))
#define CP_COMMIT() asm volatile("cp.async.commit_group;" ::: "memory")
#define CP_WAIT(n)  asm volatile("cp.async.wait_group %0;" :: "n"(n) : "memory")

__device__ __forceinline__ void ldsm_x4(uint32_t& r0, uint32_t& r1,
                                        uint32_t& r2, uint32_t& r3, uint32_t a) {
    asm volatile("ldmatrix.sync.aligned.m8n8.x4.shared.b16 {%0,%1,%2,%3}, [%4];"
                 : "=r"(r0), "=r"(r1), "=r"(r2), "=r"(r3) : "r"(a));
}

// f16 in, f16 accumulate (2 packed half2 regs for C/D)
__device__ __forceinline__ void mma_f16acc(uint32_t& c0, uint32_t& c1,
                                           uint32_t a0, uint32_t a1, uint32_t a2, uint32_t a3,
                                           uint32_t b0, uint32_t b1) {
    asm volatile(
        "mma.sync.aligned.m16n8k16.row.col.f16.f16.f16.f16 "
        "{%0,%1}, {%2,%3,%4,%5}, {%6,%7}, {%0,%1};"
        : "+r"(c0), "+r"(c1)
        : "r"(a0), "r"(a1), "r"(a2), "r"(a3), "r"(b0), "r"(b1));
}

// Swizzled byte offset within a [rows][64B] tile (64B rows, 16B chunks)
__device__ __forceinline__ uint32_t sw_off(int r, int c) {
    return (uint32_t)(r * 64 + ((c ^ ((r >> 1) & 3)) << 4));
}

// ---------------------------------------------------------------------------
// Kernel 1: per-row norms, exact fp32 ap, f16 normalized vectors
// ---------------------------------------------------------------------------
__global__ __launch_bounds__(256) void normalize_kernel(
    const float* __restrict__ A, const float* __restrict__ P)
{
    const int r   = blockIdx.x;
    const int tid = threadIdx.x;

    const float4 av = reinterpret_cast<const float4*>(A + (size_t)r * EDIM)[tid];
    const float4 pv = reinterpret_cast<const float4*>(P + (size_t)r * EDIM)[tid];

    float sa  = av.x*av.x + av.y*av.y + av.z*av.z + av.w*av.w;
    float sp  = pv.x*pv.x + pv.y*pv.y + pv.z*pv.z + pv.w*pv.w;
    float sap = av.x*pv.x + av.y*pv.y + av.z*pv.z + av.w*pv.w;

    #pragma unroll
    for (int o = 16; o > 0; o >>= 1) {
        sa  += __shfl_xor_sync(0xffffffffu, sa,  o);
        sp  += __shfl_xor_sync(0xffffffffu, sp,  o);
        sap += __shfl_xor_sync(0xffffffffu, sap, o);
    }

    __shared__ float sh[3][8];
    __shared__ float bc[2];
    const int w = tid >> 5, l = tid & 31;
    if (l == 0) { sh[0][w] = sa; sh[1][w] = sp; sh[2][w] = sap; }
    __syncthreads();

    if (tid == 0) {
        float ta = 0.f, tp = 0.f, tap = 0.f;
        #pragma unroll
        for (int i = 0; i < 8; ++i) { ta += sh[0][i]; tp += sh[1][i]; tap += sh[2][i]; }
        g_ap[r]  = tap / fmaxf(sqrtf(ta) * sqrtf(tp), 1e-8f);
        float rna = rsqrtf(ta), rnp = rsqrtf(tp);
        g_rna[r] = rna;
        g_rnp[r] = rnp;
        g_neg[r] = 0xFFFFFFFFFFFFFFFFull;
        bc[0] = rna;
        bc[1] = rnp;
    }
    __syncthreads();

    const float qa = bc[0], qp = bc[1];
    __half2* da = reinterpret_cast<__half2*>(g_A16 + (size_t)r * EDIM);
    __half2* dp = reinterpret_cast<__half2*>(g_P16 + (size_t)r * EDIM);
    da[tid*2 + 0] = __floats2half2_rn(av.x * qa, av.y * qa);
    da[tid*2 + 1] = __floats2half2_rn(av.z * qa, av.w * qa);
    dp[tid*2 + 0] = __floats2half2_rn(pv.x * qp, pv.y * qp);
    dp[tid*2 + 1] = __floats2half2_rn(pv.z * qp, pv.w * qp);
}

// ---------------------------------------------------------------------------
// Kernel 2: f16 mma.sync (f16 accum) GEMM with fused per-row argmin epilogue.
// 128x256 CTA tile, BK=32, 4-stage cp.async pipeline, 8 warps, 2 CTAs/SM.
// ---------------------------------------------------------------------------
__device__ __forceinline__ void load_stage(uint32_t sbase, int slot, int chunk,
                                           int row0, int col0, int tid)
{
    const size_t k0b = (size_t)chunk * (BK * 2);
    const char* Ab = (const char*)g_A16;
    const char* Bb = (const char*)g_P16;

    const uint32_t ad0 = sbase + slot * A_STAGE_BYTES;
    #pragma unroll
    for (int i = 0; i < 2; ++i) {                   // 512 chunks of 16B
        int u = i * 256 + tid;
        int r = u >> 2, c = u & 3;
        CP_ASYNC16(ad0 + sw_off(r, c),
                   Ab + (size_t)(row0 + r) * (EDIM * 2) + k0b + c * 16);
    }
    const uint32_t bd0 = sbase + B_BASE_OFF + slot * B_STAGE_BYTES;
    #pragma unroll
    for (int i = 0; i < 4; ++i) {                   // 1024 chunks of 16B
        int u = i * 256 + tid;
        int r = u >> 2, c = u & 3;
        CP_ASYNC16(bd0 + sw_off(r, c),
                   Bb + (size_t)(col0 + r) * (EDIM * 2) + k0b + c * 16);
    }
}

__global__ __launch_bounds__(256, 2) void gemm_min_f16()
{
    extern __shared__ char dynsmem[];
    const uint32_t sbase = (uint32_t)__cvta_generic_to_shared(dynsmem);

    const int tid   = threadIdx.x;
    const int wid   = tid >> 5;
    const int lane  = tid & 31;
    const int wm    = wid >> 2;          // 0..1
    const int wn    = wid & 3;           // 0..3
    const int row0  = blockIdx.y * TM;
    const int col0  = blockIdx.x * TN;

    const int mi = lane >> 3;
    const int lr = lane & 7;

    // f16 accumulators: [mt][nf][g] g=0 rows 0-7, g=1 rows 8-15 (packed half2)
    uint32_t acc[4][8][2];
    #pragma unroll
    for (int mt = 0; mt < 4; ++mt)
        #pragma unroll
        for (int nf = 0; nf < 8; ++nf) { acc[mt][nf][0] = 0u; acc[mt][nf][1] = 0u; }

    #pragma unroll
    for (int s = 0; s < STAGES - 1; ++s) {
        load_stage(sbase, s, s, row0, col0, tid);
        CP_COMMIT();
    }

    for (int c = 0; c < NCHUNK; ++c) {
        const int s = c & (STAGES - 1);

        if      (c <= NCHUNK - 3) CP_WAIT(2);
        else if (c == NCHUNK - 2) CP_WAIT(1);
        else                      CP_WAIT(0);
        __syncthreads();

        if (c + STAGES - 1 < NCHUNK) {
            load_stage(sbase, (c + STAGES - 1) & (STAGES - 1),
                       c + STAGES - 1, row0, col0, tid);
            CP_COMMIT();
        }

        const uint32_t aS = sbase + s * A_STAGE_BYTES;
        const uint32_t bS = sbase + B_BASE_OFF + s * B_STAGE_BYTES;

        #pragma unroll
        for (int h = 0; h < 2; ++h) {          // two k16 halves of BK=32
            uint32_t af[4][4];
            uint32_t bf[8][2];
            #pragma unroll
            for (int mt = 0; mt < 4; ++mt) {
                const int r = wm * 64 + mt * 16 + (mi & 1) * 8 + lr;
                const int ch = 2 * h + (mi >> 1);
                ldsm_x4(af[mt][0], af[mt][1], af[mt][2], af[mt][3],
                        aS + sw_off(r, ch));
            }
            #pragma unroll
            for (int nt = 0; nt < 4; ++nt) {
                const int r = wn * 64 + nt * 16 + (mi & 1) * 8 + lr;
                const int ch = 2 * h + (mi >> 1);
                uint32_t r0, r1, r2, r3;
                ldsm_x4(r0, r1, r2, r3, bS + sw_off(r, ch));
                bf[2*nt][0]   = r0; bf[2*nt][1]   = r2;
                bf[2*nt+1][0] = r1; bf[2*nt+1][1] = r3;
            }
            #pragma unroll
            for (int mt = 0; mt < 4; ++mt)
                #pragma unroll
                for (int nf = 0; nf < 8; ++nf)
                    mma_f16acc(acc[mt][nf][0], acc[mt][nf][1],
                               af[mt][0], af[mt][1], af[mt][2], af[mt][3],
                               bf[nf][0], bf[nf][1]);
        }
        __syncthreads();
    }

    // Epilogue: per-row (min value, col index) packed argmin, excl. diagonal.
    #pragma unroll
    for (int mt = 0; mt < 4; ++mt) {
        const int r_lo = row0 + wm * 64 + mt * 16 + (lane >> 2);
        const int r_hi = r_lo + 8;
        unsigned long long plo = 0xFFFFFFFFFFFFFFFFull;
        unsigned long long phi = 0xFFFFFFFFFFFFFFFFull;
        #pragma unroll
        for (int nf = 0; nf < 8; ++nf) {
            const __half2 vlo2 = *reinterpret_cast<const __half2*>(&acc[mt][nf][0]);
            const __half2 vhi2 = *reinterpret_cast<const __half2*>(&acc[mt][nf][1]);
            const float vl[2] = { __low2float(vlo2), __high2float(vlo2) };
            const float vh[2] = { __low2float(vhi2), __high2float(vhi2) };
            #pragma unroll
            for (int e = 0; e < 2; ++e) {
                const int gj = col0 + wn * 64 + nf * 8 + (lane & 3) * 2 + e;
                const unsigned long long klo =
                    ((unsigned long long)fenc(vl[e]) << 32) | (unsigned)gj;
                const unsigned long long khi =
                    ((unsigned long long)fenc(vh[e]) << 32) | (unsigned)gj;
                if (gj != r_lo && klo < plo) plo = klo;
                if (gj != r_hi && khi < phi) phi = khi;
            }
        }
        #pragma unroll
        for (int o = 1; o <= 2; o <<= 1) {
            unsigned long long t;
            t = __shfl_xor_sync(0xffffffffu, plo, o); if (t < plo) plo = t;
            t = __shfl_xor_sync(0xffffffffu, phi, o); if (t < phi) phi = t;
        }
        if ((lane & 3) == 0) {
            atomicMin(&g_neg[r_lo], plo);
            atomicMin(&g_neg[r_hi], phi);
        }
    }
}

// ---------------------------------------------------------------------------
// Kernel 3: exact fp32 recompute of an for the selected column; per-row term.
// ---------------------------------------------------------------------------
__global__ __launch_bounds__(256) void an_term_kernel(
    const float* __restrict__ A, const float* __restrict__ P)
{
    const int r   = blockIdx.x;
    const int tid = threadIdx.x;
    const int j   = (int)(unsigned)(g_neg[r] & 0xFFFFFFFFull);

    const float4 av = reinterpret_cast<const float4*>(A + (size_t)r * EDIM)[tid];
    const float4 pv = reinterpret_cast<const float4*>(P + (size_t)j * EDIM)[tid];
    float s = av.x*pv.x + av.y*pv.y + av.z*pv.z + av.w*pv.w;

    #pragma unroll
    for (int o = 16; o > 0; o >>= 1) s += __shfl_xor_sync(0xffffffffu, s, o);

    __shared__ float sh[8];
    const int w = tid >> 5, l = tid & 31;
    if (l == 0) sh[w] = s;
    __syncthreads();
    if (tid == 0) {
        float t = 0.f;
        #pragma unroll
        for (int i = 0; i < 8; ++i) t += sh[i];
        const float an = t * g_rna[r] * g_rnp[j];
        g_term[r] = fmaxf(1.0f + g_ap[r] - an, 0.f);
    }
}

// ---------------------------------------------------------------------------
// Kernel 4: mean over terms
// ---------------------------------------------------------------------------
__global__ __launch_bounds__(256) void loss_kernel(float* __restrict__ out, int B)
{
    const int tid = threadIdx.x;
    float s = 0.f;
    for (int r = tid; r < B; r += 256) s += g_term[r];
    #pragma unroll
    for (int o = 16; o > 0; o >>= 1) s += __shfl_xor_sync(0xffffffffu, s, o);

    __shared__ float sh[8];
    const int w = tid >> 5, l = tid & 31;
    if (l == 0) sh[w] = s;
    __syncthreads();
    if (tid == 0) {
        float t = 0.f;
        #pragma unroll
        for (int i = 0; i < 8; ++i) t += sh[i];
        out[0] = t / (float)B;
    }
}

extern "C" void kernel_launch(void* const* d_in, const int* in_sizes, int n_in,
                              void* d_out, int out_size)
{
    const float* anchor   = (const float*)d_in[0];
    const float* positive = (const float*)d_in[1];
    float* out = (float*)d_out;

    const int B = in_sizes[0] / EDIM;   // 8192

    cudaFuncSetAttribute(gemm_min_f16,
                         cudaFuncAttributeMaxDynamicSharedMemorySize, SMEM_DYN);

    normalize_kernel<<<B, 256>>>(anchor, positive);
    dim3 grid(B / TN, B / TM);
    gemm_min_f16<<<grid, 256, SMEM_DYN>>>();
    an_term_kernel<<<B, 256>>>(anchor, positive);
    loss_kernel<<<1, 256>>>(out, B);
}